// round 1
// baseline (speedup 1.0000x reference)
#include <cuda_runtime.h>
#include <math.h>
#include <stdint.h>

// ---------------- problem constants ----------------
constexpr int   B_  = 8;
constexpr int   T_  = 2048;
constexpr int   D_  = 1024;
constexpr int   H_  = 16;
constexpr int   HD_ = 64;
constexpr size_t BTD = (size_t)B_ * T_ * D_;   // 16,777,216
constexpr size_t BT  = (size_t)B_ * T_;        // 16,384
constexpr float LOG_W_SCALE = -0.6065306597126334f;
constexpr float GN_EPS = (float)HD_ * 1e-5f;   // 6.4e-4

// ---------------- scratch pool (device global; no allocations) ----------------
// slots of BTD floats:
// 0:XR 1:XW 2:XK 3:XV 4:XA 5:XG 6:R 7:EW 8:K 9:V 10:AKK 11:BKK 12:A 13:VMIX 14:O 15:G 16:GATED
constexpr size_t N_SLOTS = 17;
constexpr size_t T1_OFF = N_SLOTS * BTD;            // BT*64   (tanh(xw@w1))
constexpr size_t T2_OFF = T1_OFF + BT * 64;         // BT*64   (xa@a1)
constexpr size_t T3_OFF = T2_OFF + BT * 64;         // BT*32   (xv@v1)
constexpr size_t T4_OFF = T3_OFF + BT * 32;         // BT*160  (sigmoid(xg@g1))
constexpr size_t SCRATCH_FLOATS = T4_OFF + BT * 160;

__device__ float g_scratch[SCRATCH_FLOATS];

// ---------------- kernel 1: token-shift mixes ----------------
__global__ void mix_kernel(const float* __restrict__ x,
                           const float* __restrict__ x_x,
                           float* __restrict__ out /* 6 x BTD */) {
    size_t idx = (size_t)blockIdx.x * blockDim.x + threadIdx.x;
    if (idx >= BTD) return;
    int d = (int)(idx & (D_ - 1));
    int t = (int)((idx >> 10) & (T_ - 1));
    float xv = x[idx];
    float prev = (t > 0) ? x[idx - D_] : 0.0f;
    float delta = prev - xv;
#pragma unroll
    for (int j = 0; j < 6; j++) {
        out[(size_t)j * BTD + idx] = xv + delta * __ldg(&x_x[j * D_ + d]);
    }
}

// ---------------- kernel 2: generic fp32 GEMM with epilogue ----------------
// C[M,N] = epilogue(A[M,K] @ Bm[K,N])
// modes: 0 none, 1 tanh, 2 exp(LOG_W_SCALE*sigmoid(bias+x)), 3 sigmoid(bias+x), 4 sigmoid(x)
#define GBM 128
#define GBN 128
#define GBK 8
__global__ __launch_bounds__(256, 2)
void gemm_kernel(const float* __restrict__ A, const float* __restrict__ Bm,
                 float* __restrict__ C, int M, int N, int K,
                 int mode, const float* __restrict__ bias) {
    __shared__ float As[GBK][GBM + 4];
    __shared__ float Bs[GBK][GBN];
    int block_row = blockIdx.y * GBM;
    int block_col = blockIdx.x * GBN;
    int tid = threadIdx.x;
    int tr = tid >> 4;          // 0..15
    int tc = tid & 15;          // 0..15
    float acc[8][8];
#pragma unroll
    for (int i = 0; i < 8; i++)
#pragma unroll
        for (int j = 0; j < 8; j++) acc[i][j] = 0.0f;

    for (int k0 = 0; k0 < K; k0 += GBK) {
        // load A tile 128x8 (M is always a multiple of 128, K a multiple of 8)
#pragma unroll
        for (int i = 0; i < 4; i++) {
            int lin = tid + i * 256;
            int r = lin >> 3, c = lin & 7;
            As[c][r] = A[(size_t)(block_row + r) * K + (k0 + c)];
        }
        // load B tile 8x128
#pragma unroll
        for (int i = 0; i < 4; i++) {
            int lin = tid + i * 256;
            int r = lin >> 7, c = lin & 127;
            int col = block_col + c;
            Bs[r][c] = (col < N) ? Bm[(size_t)(k0 + r) * N + col] : 0.0f;
        }
        __syncthreads();
#pragma unroll
        for (int kk = 0; kk < GBK; kk++) {
            float af[8], bf[8];
#pragma unroll
            for (int i = 0; i < 8; i++) af[i] = As[kk][tr * 8 + i];
#pragma unroll
            for (int j = 0; j < 8; j++) bf[j] = Bs[kk][tc * 8 + j];
#pragma unroll
            for (int i = 0; i < 8; i++)
#pragma unroll
                for (int j = 0; j < 8; j++) acc[i][j] += af[i] * bf[j];
        }
        __syncthreads();
    }

#pragma unroll
    for (int i = 0; i < 8; i++) {
        int row = block_row + tr * 8 + i;
#pragma unroll
        for (int j = 0; j < 8; j++) {
            int col = block_col + tc * 8 + j;
            if (col < N) {
                float v = acc[i][j];
                if (mode == 1) {
                    v = tanhf(v);
                } else if (mode == 2) {
                    float s = 1.0f / (1.0f + expf(-(bias[col] + v)));
                    v = expf(LOG_W_SCALE * s);
                } else if (mode == 3) {
                    v = 1.0f / (1.0f + expf(-(bias[col] + v)));
                } else if (mode == 4) {
                    v = 1.0f / (1.0f + expf(-v));
                }
                C[(size_t)row * N + col] = v;
            }
        }
    }
}

// ---------------- kernel 3: prep (kk normalize, k/v updates, scan a/b inputs) ----------------
// grid = BT blocks, 512 threads (one warp per head, 2 elems per lane)
__global__ void prep_kernel(float* __restrict__ Kb, float* __restrict__ Vb,
                            const float* __restrict__ Ab, const float* __restrict__ VMIXb,
                            const float* __restrict__ vfirst,
                            const float* __restrict__ k_k, const float* __restrict__ k_a,
                            float* __restrict__ AKK, float* __restrict__ BKK) {
    int bt = blockIdx.x;
    int lane = threadIdx.x & 31;
    int h = threadIdx.x >> 5;
    int d0 = h * HD_ + lane, d1 = d0 + 32;
    size_t i0 = (size_t)bt * D_ + d0;
    size_t i1 = i0 + 32;

    float k0 = Kb[i0], k1 = Kb[i1];
    float kk0 = k0 * __ldg(&k_k[d0]);
    float kk1 = k1 * __ldg(&k_k[d1]);
    float ss = kk0 * kk0 + kk1 * kk1;
#pragma unroll
    for (int o = 16; o > 0; o >>= 1) ss += __shfl_xor_sync(0xffffffffu, ss, o);
    float inv = 1.0f / fmaxf(sqrtf(ss), 1e-12f);
    kk0 *= inv; kk1 *= inv;

    float a0v = Ab[i0], a1v = Ab[i1];
    AKK[i0] = -kk0;        AKK[i1] = -kk1;
    BKK[i0] = kk0 * a0v;   BKK[i1] = kk1 * a1v;

    Kb[i0] = k0 * (1.0f + (a0v - 1.0f) * __ldg(&k_a[d0]));
    Kb[i1] = k1 * (1.0f + (a1v - 1.0f) * __ldg(&k_a[d1]));

    float v0v = Vb[i0], v1v = Vb[i1];
    Vb[i0] = v0v + (vfirst[i0] - v0v) * VMIXb[i0];
    Vb[i1] = v1v + (vfirst[i1] - v1v) * VMIXb[i1];
}

// ---------------- kernel 4: sequential delta-rule scan ----------------
// SC points at R; arrays at SC + arr*BTD in order: R(0) EW(1) K(2) V(3) AKK(4) BKK(5)
// grid = B*H blocks; 256 threads: row i = tid>>2 (V index), col-group c = tid&3 (16 K cols)
__global__ __launch_bounds__(256, 1)
void scan_kernel(const float* __restrict__ SC, float* __restrict__ O) {
    int b = blockIdx.x >> 4;
    int h = blockIdx.x & 15;
    int tid = threadIdx.x;
    int i = tid >> 2;
    int c = tid & 3;
    int cb = c * 16;

    __shared__ float sh[6][64];
    float S[16];
#pragma unroll
    for (int j = 0; j < 16; j++) S[j] = 0.0f;

    size_t base = (size_t)b * T_ * D_ + (size_t)h * HD_;
    const unsigned FULL = 0xffffffffu;

    for (int t = 0; t < T_; t++) {
        // stage 6x64 floats
        {
            int j = tid;
            sh[j >> 6][j & 63] = SC[(size_t)(j >> 6) * BTD + base + (j & 63)];
            j = tid + 256;
            if (j < 384)
                sh[j >> 6][j & 63] = SC[(size_t)(j >> 6) * BTD + base + (j & 63)];
        }
        __syncthreads();

        float sa = 0.0f;
#pragma unroll
        for (int j = 0; j < 16; j++) sa += S[j] * sh[4][cb + j];
        sa += __shfl_xor_sync(FULL, sa, 1);
        sa += __shfl_xor_sync(FULL, sa, 2);

        float vi = sh[3][i];
        float op = 0.0f;
#pragma unroll
        for (int j = 0; j < 16; j++) {
            float tmp = sa * sh[5][cb + j] + vi * sh[2][cb + j];
            S[j] = S[j] * sh[1][cb + j] + tmp;
            op += S[j] * sh[0][cb + j];
        }
        op += __shfl_xor_sync(FULL, op, 1);
        op += __shfl_xor_sync(FULL, op, 2);
        if (c == 0) O[base + i] = op;
        __syncthreads();
        base += D_;
    }
}

// ---------------- kernel 5: groupnorm + bonus + gate ----------------
// grid = BT blocks, 512 threads (warp per head)
__global__ void post_kernel(const float* __restrict__ O, const float* __restrict__ R,
                            const float* __restrict__ Kb, const float* __restrict__ Vb,
                            const float* __restrict__ G, const float* __restrict__ r_k,
                            const float* __restrict__ gn_w, const float* __restrict__ gn_b,
                            float* __restrict__ GATED) {
    int bt = blockIdx.x;
    int lane = threadIdx.x & 31;
    int h = threadIdx.x >> 5;
    int d0 = h * HD_ + lane, d1 = d0 + 32;
    size_t i0 = (size_t)bt * D_ + d0;
    size_t i1 = i0 + 32;

    float o0 = O[i0], o1 = O[i1];
    float s = o0 + o1;
    float sq = o0 * o0 + o1 * o1;
    float dot = R[i0] * Kb[i0] * __ldg(&r_k[d0]) + R[i1] * Kb[i1] * __ldg(&r_k[d1]);
#pragma unroll
    for (int o = 16; o > 0; o >>= 1) {
        s   += __shfl_xor_sync(0xffffffffu, s, o);
        sq  += __shfl_xor_sync(0xffffffffu, sq, o);
        dot += __shfl_xor_sync(0xffffffffu, dot, o);
    }
    float mean = s * (1.0f / 64.0f);
    float var = sq * (1.0f / 64.0f) - mean * mean;
    float rstd = rsqrtf(var + GN_EPS);
    float on0 = (o0 - mean) * rstd * __ldg(&gn_w[d0]) + __ldg(&gn_b[d0]);
    float on1 = (o1 - mean) * rstd * __ldg(&gn_w[d1]) + __ldg(&gn_b[d1]);
    on0 += dot * Vb[i0];
    on1 += dot * Vb[i1];
    GATED[i0] = on0 * G[i0];
    GATED[i1] = on1 * G[i1];
}

// ---------------- host launcher ----------------
static void run_gemm(const float* A, const float* Bm, float* C,
                     int M, int N, int K, int mode, const float* bias) {
    dim3 grid((N + GBN - 1) / GBN, (M + GBM - 1) / GBM);
    gemm_kernel<<<grid, 256>>>(A, Bm, C, M, N, K, mode, bias);
}

extern "C" void kernel_launch(void* const* d_in, const int* in_sizes, int n_in,
                              void* d_out, int out_size) {
    const float* x       = (const float*)d_in[0];
    const float* v_first = (const float*)d_in[1];
    const float* x_x     = (const float*)d_in[2];
    const float* W_r     = (const float*)d_in[3];
    const float* W_k     = (const float*)d_in[4];
    const float* W_v     = (const float*)d_in[5];
    const float* W_o     = (const float*)d_in[6];
    const float* w1      = (const float*)d_in[7];
    const float* w2      = (const float*)d_in[8];
    const float* w0      = (const float*)d_in[9];
    const float* a1      = (const float*)d_in[10];
    const float* a2      = (const float*)d_in[11];
    const float* a0      = (const float*)d_in[12];
    const float* v1      = (const float*)d_in[13];
    const float* v2      = (const float*)d_in[14];
    const float* v0      = (const float*)d_in[15];
    const float* g1      = (const float*)d_in[16];
    const float* g2      = (const float*)d_in[17];
    const float* k_k     = (const float*)d_in[18];
    const float* k_a     = (const float*)d_in[19];
    const float* r_k     = (const float*)d_in[20];
    const float* gn_w    = (const float*)d_in[21];
    const float* gn_b    = (const float*)d_in[22];
    float* out = (float*)d_out;

    float* sc;
    cudaGetSymbolAddress((void**)&sc, g_scratch);

    float* XR    = sc + 0 * BTD;
    float* XW    = sc + 1 * BTD;
    float* XK    = sc + 2 * BTD;
    float* XV    = sc + 3 * BTD;
    float* XA    = sc + 4 * BTD;
    float* XG    = sc + 5 * BTD;
    float* Rb    = sc + 6 * BTD;
    float* EWb   = sc + 7 * BTD;
    float* Kb    = sc + 8 * BTD;
    float* Vb    = sc + 9 * BTD;
    float* AKKb  = sc + 10 * BTD;
    float* BKKb  = sc + 11 * BTD;
    float* Ab    = sc + 12 * BTD;
    float* VMIXb = sc + 13 * BTD;
    float* Ob    = sc + 14 * BTD;
    float* Gb    = sc + 15 * BTD;
    float* GATED = sc + 16 * BTD;
    float* T1b   = sc + T1_OFF;
    float* T2b   = sc + T2_OFF;
    float* T3b   = sc + T3_OFF;
    float* T4b   = sc + T4_OFF;

    // 1. token-shift mixes
    mix_kernel<<<(unsigned)((BTD + 255) / 256), 256>>>(x, x_x, XR);

    // 2. big projections
    run_gemm(XR, W_r, Rb, (int)BT, D_, D_, 0, nullptr);
    run_gemm(XK, W_k, Kb, (int)BT, D_, D_, 0, nullptr);
    run_gemm(XV, W_v, Vb, (int)BT, D_, D_, 0, nullptr);

    // 3. low-rank chains
    run_gemm(XW, w1, T1b, (int)BT, 64, D_, 1, nullptr);          // tanh(xw@w1)
    run_gemm(T1b, w2, EWb, (int)BT, D_, 64, 2, w0);              // exp(scale*sigmoid(w0+.))
    run_gemm(XA, a1, T2b, (int)BT, 64, D_, 0, nullptr);
    run_gemm(T2b, a2, Ab, (int)BT, D_, 64, 3, a0);               // sigmoid(a0+.)
    run_gemm(XV, v1, T3b, (int)BT, 32, D_, 0, nullptr);
    run_gemm(T3b, v2, VMIXb, (int)BT, D_, 32, 3, v0);            // sigmoid(v0+.)
    run_gemm(XG, g1, T4b, (int)BT, 160, D_, 4, nullptr);         // sigmoid(xg@g1)
    run_gemm(T4b, g2, Gb, (int)BT, D_, 160, 0, nullptr);

    // 4. prep: kk normalize, a/b scan inputs, k & v updates
    prep_kernel<<<(unsigned)BT, 512>>>(Kb, Vb, Ab, VMIXb, v_first, k_k, k_a, AKKb, BKKb);

    // 5. sequential scan
    scan_kernel<<<B_ * H_, 256>>>(Rb, Ob);

    // 6. groupnorm + bonus + gate
    post_kernel<<<(unsigned)BT, 512>>>(Ob, Rb, Kb, Vb, Gb, r_k, gn_w, gn_b, GATED);

    // 7. output projection
    run_gemm(GATED, W_o, out, (int)BT, D_, D_, 0, nullptr);

    // 8. v_first passthrough
    if ((size_t)out_size >= 2 * BTD) {
        cudaMemcpyAsync(out + BTD, v_first, BTD * sizeof(float),
                        cudaMemcpyDeviceToDevice, 0);
    }
}

// round 3
// speedup vs baseline: 1.8121x; 1.8121x over previous
#include <cuda_runtime.h>
#include <math.h>
#include <stdint.h>

// ---------------- problem constants ----------------
constexpr int   B_  = 8;
constexpr int   T_  = 2048;
constexpr int   D_  = 1024;
constexpr int   H_  = 16;
constexpr int   HD_ = 64;
constexpr size_t BTD = (size_t)B_ * T_ * D_;   // 16,777,216
constexpr size_t BT  = (size_t)B_ * T_;        // 16,384
constexpr float LOG_W_SCALE = -0.6065306597126334f;
constexpr float GN_EPS = (float)HD_ * 1e-5f;

// ---------------- scratch pool ----------------
constexpr size_t N_SLOTS = 17;
constexpr size_t T1_OFF = N_SLOTS * BTD;
constexpr size_t T2_OFF = T1_OFF + BT * 64;
constexpr size_t T3_OFF = T2_OFF + BT * 64;
constexpr size_t T4_OFF = T3_OFF + BT * 32;
constexpr size_t WT_OFF  = T4_OFF + BT * 160;
constexpr size_t WRT_OFF = WT_OFF;
constexpr size_t WKT_OFF = WRT_OFF + (size_t)D_ * D_;
constexpr size_t WVT_OFF = WKT_OFF + (size_t)D_ * D_;
constexpr size_t WOT_OFF = WVT_OFF + (size_t)D_ * D_;
constexpr size_t W1T_OFF = WOT_OFF + (size_t)D_ * D_;
constexpr size_t W2T_OFF = W1T_OFF + (size_t)64 * 1024;
constexpr size_t A1T_OFF = W2T_OFF + (size_t)64 * 1024;
constexpr size_t A2T_OFF = A1T_OFF + (size_t)64 * 1024;
constexpr size_t V1T_OFF = A2T_OFF + (size_t)64 * 1024;
constexpr size_t V2T_OFF = V1T_OFF + (size_t)32 * 1024;
constexpr size_t G1T_OFF = V2T_OFF + (size_t)32 * 1024;
constexpr size_t G2T_OFF = G1T_OFF + (size_t)160 * 1024;
constexpr size_t SCRATCH_FLOATS = G2T_OFF + (size_t)160 * 1024;

__device__ float g_scratch[SCRATCH_FLOATS];

// ---------------- helpers ----------------
__device__ __forceinline__ uint32_t tf32bits(float x) {
    uint32_t y;
    asm("cvt.rna.tf32.f32 %0, %1;" : "=r"(y) : "f"(x));
    return y;
}
__device__ __forceinline__ void mma_tf32(float& c0, float& c1, float& c2, float& c3,
                                         uint32_t a0, uint32_t a1, uint32_t a2, uint32_t a3,
                                         uint32_t b0, uint32_t b1) {
    asm volatile(
        "mma.sync.aligned.m16n8k8.row.col.f32.tf32.tf32.f32 "
        "{%0,%1,%2,%3}, {%4,%5,%6,%7}, {%8,%9}, {%0,%1,%2,%3};"
        : "+f"(c0), "+f"(c1), "+f"(c2), "+f"(c3)
        : "r"(a0), "r"(a1), "r"(a2), "r"(a3), "r"(b0), "r"(b1));
}
__device__ __forceinline__ float apply_epi(float f, int mode,
                                           const float* __restrict__ bias, int colg) {
    if (mode == 1) {
        f = tanhf(f);
    } else if (mode == 2) {
        float s = 1.0f / (1.0f + expf(-(__ldg(&bias[colg]) + f)));
        f = expf(LOG_W_SCALE * s);
    } else if (mode == 3) {
        f = 1.0f / (1.0f + expf(-(__ldg(&bias[colg]) + f)));
    } else if (mode == 4) {
        f = 1.0f / (1.0f + expf(-f));
    }
    return f;
}

// ---------------- kernel 1: token-shift mixes ----------------
__global__ void mix_kernel(const float* __restrict__ x,
                           const float* __restrict__ x_x,
                           float* __restrict__ out /* 6 x BTD */) {
    size_t idx = (size_t)blockIdx.x * blockDim.x + threadIdx.x;
    if (idx >= BTD) return;
    int d = (int)(idx & (D_ - 1));
    int t = (int)((idx >> 10) & (T_ - 1));
    float xv = x[idx];
    float prev = (t > 0) ? x[idx - D_] : 0.0f;
    float delta = prev - xv;
#pragma unroll
    for (int j = 0; j < 6; j++) {
        out[(size_t)j * BTD + idx] = xv + delta * __ldg(&x_x[j * D_ + d]);
    }
}

// ---------------- transpose kernel: in[K,N] -> out[N,K] ----------------
__global__ void transpose_kernel(const float* __restrict__ in, float* __restrict__ out,
                                 int K, int N) {
    __shared__ float tile[32][33];
    int n0 = blockIdx.x * 32, k0 = blockIdx.y * 32;
    int tx = threadIdx.x, ty = threadIdx.y;  // 32 x 8
#pragma unroll
    for (int i = 0; i < 32; i += 8) {
        int k = k0 + ty + i, n = n0 + tx;
        if (k < K && n < N) tile[ty + i][tx] = in[(size_t)k * N + n];
    }
    __syncthreads();
#pragma unroll
    for (int i = 0; i < 32; i += 8) {
        int n = n0 + ty + i, k = k0 + tx;
        if (n < N && k < K) out[(size_t)n * K + k] = tile[tx][ty + i];
    }
}

// ---------------- kernel 2: tf32 mma.sync GEMM ----------------
// C[M,N] = epilogue(A[M,K] @ Bt[N,K]^T)
// M % 128 == 0, K % 32 == 0, N % 8 == 0
// 256 threads, 8 warps as 2(m) x 4(n); warp tile 64x32; CTA tile 128x128, BK=32.
#define SK 36
__global__ __launch_bounds__(256)
void tgemm_kernel(const float* __restrict__ A, const float* __restrict__ Bt,
                  float* __restrict__ C, int M, int N, int K,
                  int mode, const float* __restrict__ bias) {
    __shared__ float As[128][SK];
    __shared__ float Bs[128][SK];

    int tid = threadIdx.x;
    int wid = tid >> 5, lane = tid & 31;
    int warp_m = wid >> 2;      // 0..1
    int warp_n = wid & 3;       // 0..3
    int gid = lane >> 2;        // groupID 0..7
    int tig = lane & 3;         // thread in group 0..3
    int block_row = blockIdx.y * 128;
    int block_col = blockIdx.x * 128;

    float acc[4][4][4];
#pragma unroll
    for (int mt = 0; mt < 4; mt++)
#pragma unroll
        for (int nt = 0; nt < 4; nt++)
#pragma unroll
            for (int q = 0; q < 4; q++) acc[mt][nt][q] = 0.0f;

    // per-thread gmem load coords (4 float4 per tile per operand)
    int lr[4], lc[4];
#pragma unroll
    for (int i = 0; i < 4; i++) {
        int f4 = tid + i * 256;
        lr[i] = f4 >> 3;           // row within 128
        lc[i] = (f4 & 7) * 4;      // col within 32
    }

    float4 ra[4], rb[4];
    int ntiles = K >> 5;

    // prefetch tile 0
#pragma unroll
    for (int i = 0; i < 4; i++) {
        ra[i] = *(const float4*)(A + (size_t)(block_row + lr[i]) * K + lc[i]);
        int rg = block_col + lr[i];
        rb[i] = (rg < N) ? *(const float4*)(Bt + (size_t)rg * K + lc[i])
                         : make_float4(0.f, 0.f, 0.f, 0.f);
    }

    for (int kt = 0; kt < ntiles; kt++) {
        // store staged tile to smem (with tf32 rounding)
#pragma unroll
        for (int i = 0; i < 4; i++) {
            uint4 va;
            va.x = tf32bits(ra[i].x); va.y = tf32bits(ra[i].y);
            va.z = tf32bits(ra[i].z); va.w = tf32bits(ra[i].w);
            *(uint4*)&As[lr[i]][lc[i]] = va;
            uint4 vb;
            vb.x = tf32bits(rb[i].x); vb.y = tf32bits(rb[i].y);
            vb.z = tf32bits(rb[i].z); vb.w = tf32bits(rb[i].w);
            *(uint4*)&Bs[lr[i]][lc[i]] = vb;
        }
        __syncthreads();

        // prefetch next tile
        if (kt + 1 < ntiles) {
            int k0 = (kt + 1) << 5;
#pragma unroll
            for (int i = 0; i < 4; i++) {
                ra[i] = *(const float4*)(A + (size_t)(block_row + lr[i]) * K + k0 + lc[i]);
                int rg = block_col + lr[i];
                rb[i] = (rg < N) ? *(const float4*)(Bt + (size_t)rg * K + k0 + lc[i])
                                 : make_float4(0.f, 0.f, 0.f, 0.f);
            }
        }

        // compute: 4 k-steps of 8
#pragma unroll
        for (int ks = 0; ks < 4; ks++) {
            int kk = ks * 8;
            uint32_t af[4][4];
#pragma unroll
            for (int mt = 0; mt < 4; mt++) {
                int r0 = warp_m * 64 + mt * 16 + gid;
                af[mt][0] = __float_as_uint(As[r0][kk + tig]);
                af[mt][1] = __float_as_uint(As[r0 + 8][kk + tig]);
                af[mt][2] = __float_as_uint(As[r0][kk + 4 + tig]);
                af[mt][3] = __float_as_uint(As[r0 + 8][kk + 4 + tig]);
            }
            uint32_t bf[4][2];
#pragma unroll
            for (int nt = 0; nt < 4; nt++) {
                int n0 = warp_n * 32 + nt * 8 + gid;
                bf[nt][0] = __float_as_uint(Bs[n0][kk + tig]);
                bf[nt][1] = __float_as_uint(Bs[n0][kk + 4 + tig]);
            }
#pragma unroll
            for (int mt = 0; mt < 4; mt++)
#pragma unroll
                for (int nt = 0; nt < 4; nt++)
                    mma_tf32(acc[mt][nt][0], acc[mt][nt][1], acc[mt][nt][2], acc[mt][nt][3],
                             af[mt][0], af[mt][1], af[mt][2], af[mt][3],
                             bf[nt][0], bf[nt][1]);
        }
        __syncthreads();
    }

    // epilogue
#pragma unroll
    for (int mt = 0; mt < 4; mt++) {
        int row = block_row + warp_m * 64 + mt * 16 + gid;
#pragma unroll
        for (int nt = 0; nt < 4; nt++) {
            int col0 = block_col + warp_n * 32 + nt * 8 + 2 * tig;
            if (col0 < N) {
                float2 v0, v1;
                v0.x = apply_epi(acc[mt][nt][0], mode, bias, col0);
                v0.y = apply_epi(acc[mt][nt][1], mode, bias, col0 + 1);
                v1.x = apply_epi(acc[mt][nt][2], mode, bias, col0);
                v1.y = apply_epi(acc[mt][nt][3], mode, bias, col0 + 1);
                *(float2*)(C + (size_t)row * N + col0) = v0;
                *(float2*)(C + (size_t)(row + 8) * N + col0) = v1;
            }
        }
    }
}

// ---------------- kernel 3: prep ----------------
__global__ void prep_kernel(float* __restrict__ Kb, float* __restrict__ Vb,
                            const float* __restrict__ Ab, const float* __restrict__ VMIXb,
                            const float* __restrict__ vfirst,
                            const float* __restrict__ k_k, const float* __restrict__ k_a,
                            float* __restrict__ AKK, float* __restrict__ BKK) {
    int bt = blockIdx.x;
    int lane = threadIdx.x & 31;
    int h = threadIdx.x >> 5;
    int d0 = h * HD_ + lane, d1 = d0 + 32;
    size_t i0 = (size_t)bt * D_ + d0;
    size_t i1 = i0 + 32;

    float k0 = Kb[i0], k1 = Kb[i1];
    float kk0 = k0 * __ldg(&k_k[d0]);
    float kk1 = k1 * __ldg(&k_k[d1]);
    float ss = kk0 * kk0 + kk1 * kk1;
#pragma unroll
    for (int o = 16; o > 0; o >>= 1) ss += __shfl_xor_sync(0xffffffffu, ss, o);
    float inv = 1.0f / fmaxf(sqrtf(ss), 1e-12f);
    kk0 *= inv; kk1 *= inv;

    float a0v = Ab[i0], a1v = Ab[i1];
    AKK[i0] = -kk0;        AKK[i1] = -kk1;
    BKK[i0] = kk0 * a0v;   BKK[i1] = kk1 * a1v;

    Kb[i0] = k0 * (1.0f + (a0v - 1.0f) * __ldg(&k_a[d0]));
    Kb[i1] = k1 * (1.0f + (a1v - 1.0f) * __ldg(&k_a[d1]));

    float v0v = Vb[i0], v1v = Vb[i1];
    Vb[i0] = v0v + (vfirst[i0] - v0v) * VMIXb[i0];
    Vb[i1] = v1v + (vfirst[i1] - v1v) * VMIXb[i1];
}

// ---------------- kernel 4: sequential delta-rule scan ----------------
__global__ __launch_bounds__(256, 1)
void scan_kernel(const float* __restrict__ SC, float* __restrict__ O) {
    int b = blockIdx.x >> 4;
    int h = blockIdx.x & 15;
    int tid = threadIdx.x;
    int i = tid >> 2;
    int c = tid & 3;
    int cb = c * 16;

    __shared__ float sh[6][64];
    float S[16];
#pragma unroll
    for (int j = 0; j < 16; j++) S[j] = 0.0f;

    size_t base = (size_t)b * T_ * D_ + (size_t)h * HD_;
    const unsigned FULL = 0xffffffffu;

    for (int t = 0; t < T_; t++) {
        {
            int j = tid;
            sh[j >> 6][j & 63] = SC[(size_t)(j >> 6) * BTD + base + (j & 63)];
            j = tid + 256;
            if (j < 384)
                sh[j >> 6][j & 63] = SC[(size_t)(j >> 6) * BTD + base + (j & 63)];
        }
        __syncthreads();

        float sa = 0.0f;
#pragma unroll
        for (int j = 0; j < 16; j++) sa += S[j] * sh[4][cb + j];
        sa += __shfl_xor_sync(FULL, sa, 1);
        sa += __shfl_xor_sync(FULL, sa, 2);

        float vi = sh[3][i];
        float op = 0.0f;
#pragma unroll
        for (int j = 0; j < 16; j++) {
            float tmp = sa * sh[5][cb + j] + vi * sh[2][cb + j];
            S[j] = S[j] * sh[1][cb + j] + tmp;
            op += S[j] * sh[0][cb + j];
        }
        op += __shfl_xor_sync(FULL, op, 1);
        op += __shfl_xor_sync(FULL, op, 2);
        if (c == 0) O[base + i] = op;
        __syncthreads();
        base += D_;
    }
}

// ---------------- kernel 5: groupnorm + bonus + gate ----------------
__global__ void post_kernel(const float* __restrict__ O, const float* __restrict__ R,
                            const float* __restrict__ Kb, const float* __restrict__ Vb,
                            const float* __restrict__ G, const float* __restrict__ r_k,
                            const float* __restrict__ gn_w, const float* __restrict__ gn_b,
                            float* __restrict__ GATED) {
    int bt = blockIdx.x;
    int lane = threadIdx.x & 31;
    int h = threadIdx.x >> 5;
    int d0 = h * HD_ + lane, d1 = d0 + 32;
    size_t i0 = (size_t)bt * D_ + d0;
    size_t i1 = i0 + 32;

    float o0 = O[i0], o1 = O[i1];
    float s = o0 + o1;
    float sq = o0 * o0 + o1 * o1;
    float dot = R[i0] * Kb[i0] * __ldg(&r_k[d0]) + R[i1] * Kb[i1] * __ldg(&r_k[d1]);
#pragma unroll
    for (int o = 16; o > 0; o >>= 1) {
        s   += __shfl_xor_sync(0xffffffffu, s, o);
        sq  += __shfl_xor_sync(0xffffffffu, sq, o);
        dot += __shfl_xor_sync(0xffffffffu, dot, o);
    }
    float mean = s * (1.0f / 64.0f);
    float var = sq * (1.0f / 64.0f) - mean * mean;
    float rstd = rsqrtf(var + GN_EPS);
    float on0 = (o0 - mean) * rstd * __ldg(&gn_w[d0]) + __ldg(&gn_b[d0]);
    float on1 = (o1 - mean) * rstd * __ldg(&gn_w[d1]) + __ldg(&gn_b[d1]);
    on0 += dot * Vb[i0];
    on1 += dot * Vb[i1];
    GATED[i0] = on0 * G[i0];
    GATED[i1] = on1 * G[i1];
}

// ---------------- host launchers ----------------
static void run_tgemm(const float* A, const float* Bt, float* C,
                      int M, int N, int K, int mode, const float* bias) {
    dim3 grid((N + 127) / 128, M / 128);
    tgemm_kernel<<<grid, 256>>>(A, Bt, C, M, N, K, mode, bias);
}
static void run_transpose(const float* in, float* out, int K, int N) {
    dim3 grid((N + 31) / 32, (K + 31) / 32);
    transpose_kernel<<<grid, dim3(32, 8)>>>(in, out, K, N);
}

extern "C" void kernel_launch(void* const* d_in, const int* in_sizes, int n_in,
                              void* d_out, int out_size) {
    const float* x       = (const float*)d_in[0];
    const float* v_first = (const float*)d_in[1];
    const float* x_x     = (const float*)d_in[2];
    const float* W_r     = (const float*)d_in[3];
    const float* W_k     = (const float*)d_in[4];
    const float* W_v     = (const float*)d_in[5];
    const float* W_o     = (const float*)d_in[6];
    const float* w1      = (const float*)d_in[7];
    const float* w2      = (const float*)d_in[8];
    const float* w0      = (const float*)d_in[9];
    const float* a1      = (const float*)d_in[10];
    const float* a2      = (const float*)d_in[11];
    const float* a0      = (const float*)d_in[12];
    const float* v1      = (const float*)d_in[13];
    const float* v2      = (const float*)d_in[14];
    const float* v0      = (const float*)d_in[15];
    const float* g1      = (const float*)d_in[16];
    const float* g2      = (const float*)d_in[17];
    const float* k_k     = (const float*)d_in[18];
    const float* k_a     = (const float*)d_in[19];
    const float* r_k     = (const float*)d_in[20];
    const float* gn_w    = (const float*)d_in[21];
    const float* gn_b    = (const float*)d_in[22];
    float* out = (float*)d_out;

    float* sc;
    cudaGetSymbolAddress((void**)&sc, g_scratch);

    float* XR    = sc + 0 * BTD;
    float* XW    = sc + 1 * BTD;
    float* XK    = sc + 2 * BTD;
    float* XV    = sc + 3 * BTD;
    float* XA    = sc + 4 * BTD;
    float* XG    = sc + 5 * BTD;
    float* Rb    = sc + 6 * BTD;
    float* EWb   = sc + 7 * BTD;
    float* Kb    = sc + 8 * BTD;
    float* Vb    = sc + 9 * BTD;
    float* AKKb  = sc + 10 * BTD;
    float* BKKb  = sc + 11 * BTD;
    float* Ab    = sc + 12 * BTD;
    float* VMIXb = sc + 13 * BTD;
    float* Ob    = sc + 14 * BTD;
    float* Gb    = sc + 15 * BTD;
    float* GATED = sc + 16 * BTD;
    float* T1b   = sc + T1_OFF;
    float* T2b   = sc + T2_OFF;
    float* T3b   = sc + T3_OFF;
    float* T4b   = sc + T4_OFF;
    float* WRT   = sc + WRT_OFF;
    float* WKT   = sc + WKT_OFF;
    float* WVT   = sc + WVT_OFF;
    float* WOT   = sc + WOT_OFF;
    float* W1T   = sc + W1T_OFF;
    float* W2T   = sc + W2T_OFF;
    float* A1T   = sc + A1T_OFF;
    float* A2T   = sc + A2T_OFF;
    float* V1T   = sc + V1T_OFF;
    float* V2T   = sc + V2T_OFF;
    float* G1T   = sc + G1T_OFF;
    float* G2T   = sc + G2T_OFF;

    // 0. weight transposes ([K,N] -> [N,K])
    run_transpose(W_r, WRT, D_, D_);
    run_transpose(W_k, WKT, D_, D_);
    run_transpose(W_v, WVT, D_, D_);
    run_transpose(W_o, WOT, D_, D_);
    run_transpose(w1, W1T, D_, 64);
    run_transpose(w2, W2T, 64, D_);
    run_transpose(a1, A1T, D_, 64);
    run_transpose(a2, A2T, 64, D_);
    run_transpose(v1, V1T, D_, 32);
    run_transpose(v2, V2T, 32, D_);
    run_transpose(g1, G1T, D_, 160);
    run_transpose(g2, G2T, 160, D_);

    // 1. token-shift mixes
    mix_kernel<<<(unsigned)((BTD + 255) / 256), 256>>>(x, x_x, XR);

    // 2. big projections (tf32 mma.sync)
    run_tgemm(XR, WRT, Rb, (int)BT, D_, D_, 0, nullptr);
    run_tgemm(XK, WKT, Kb, (int)BT, D_, D_, 0, nullptr);
    run_tgemm(XV, WVT, Vb, (int)BT, D_, D_, 0, nullptr);

    // 3. low-rank chains
    run_tgemm(XW, W1T, T1b, (int)BT, 64, D_, 1, nullptr);
    run_tgemm(T1b, W2T, EWb, (int)BT, D_, 64, 2, w0);
    run_tgemm(XA, A1T, T2b, (int)BT, 64, D_, 0, nullptr);
    run_tgemm(T2b, A2T, Ab, (int)BT, D_, 64, 3, a0);
    run_tgemm(XV, V1T, T3b, (int)BT, 32, D_, 0, nullptr);
    run_tgemm(T3b, V2T, VMIXb, (int)BT, D_, 32, 3, v0);
    run_tgemm(XG, G1T, T4b, (int)BT, 160, D_, 4, nullptr);
    run_tgemm(T4b, G2T, Gb, (int)BT, D_, 160, 0, nullptr);

    // 4. prep
    prep_kernel<<<(unsigned)BT, 512>>>(Kb, Vb, Ab, VMIXb, v_first, k_k, k_a, AKKb, BKKb);

    // 5. sequential scan
    scan_kernel<<<B_ * H_, 256>>>(Rb, Ob);

    // 6. groupnorm + bonus + gate
    post_kernel<<<(unsigned)BT, 512>>>(Ob, Rb, Kb, Vb, Gb, r_k, gn_w, gn_b, GATED);

    // 7. output projection
    run_tgemm(GATED, WOT, out, (int)BT, D_, D_, 0, nullptr);

    // 8. v_first passthrough
    if ((size_t)out_size >= 2 * BTD) {
        cudaMemcpyAsync(out + BTD, v_first, BTD * sizeof(float),
                        cudaMemcpyDeviceToDevice, 0);
    }
}

// round 4
// speedup vs baseline: 2.4515x; 1.3529x over previous
#include <cuda_runtime.h>
#include <math.h>
#include <stdint.h>

// ---------------- problem constants ----------------
constexpr int   B_  = 8;
constexpr int   T_  = 2048;
constexpr int   D_  = 1024;
constexpr int   H_  = 16;
constexpr int   HD_ = 64;
constexpr size_t BTD = (size_t)B_ * T_ * D_;   // 16,777,216
constexpr size_t BT  = (size_t)B_ * T_;        // 16,384
constexpr float LOG_W_SCALE = -0.6065306597126334f;
constexpr float GN_EPS = (float)HD_ * 1e-5f;

// ---------------- scratch pool ----------------
constexpr size_t N_SLOTS = 17;
constexpr size_t T1_OFF = N_SLOTS * BTD;
constexpr size_t T2_OFF = T1_OFF + BT * 64;
constexpr size_t T3_OFF = T2_OFF + BT * 64;
constexpr size_t T4_OFF = T3_OFF + BT * 32;
constexpr size_t WT_OFF  = T4_OFF + BT * 160;
constexpr size_t WRT_OFF = WT_OFF;
constexpr size_t WKT_OFF = WRT_OFF + (size_t)D_ * D_;
constexpr size_t WVT_OFF = WKT_OFF + (size_t)D_ * D_;
constexpr size_t WOT_OFF = WVT_OFF + (size_t)D_ * D_;
constexpr size_t W1T_OFF = WOT_OFF + (size_t)D_ * D_;
constexpr size_t W2T_OFF = W1T_OFF + (size_t)64 * 1024;
constexpr size_t A1T_OFF = W2T_OFF + (size_t)64 * 1024;
constexpr size_t A2T_OFF = A1T_OFF + (size_t)64 * 1024;
constexpr size_t V1T_OFF = A2T_OFF + (size_t)64 * 1024;
constexpr size_t V2T_OFF = V1T_OFF + (size_t)32 * 1024;
constexpr size_t G1T_OFF = V2T_OFF + (size_t)32 * 1024;
constexpr size_t G2T_OFF = G1T_OFF + (size_t)160 * 1024;
constexpr size_t SCRATCH_FLOATS = G2T_OFF + (size_t)160 * 1024;

__device__ float g_scratch[SCRATCH_FLOATS];

// ---------------- helpers ----------------
__device__ __forceinline__ uint32_t tf32bits(float x) {
    uint32_t y;
    asm("cvt.rna.tf32.f32 %0, %1;" : "=r"(y) : "f"(x));
    return y;
}
__device__ __forceinline__ void mma_tf32(float& c0, float& c1, float& c2, float& c3,
                                         uint32_t a0, uint32_t a1, uint32_t a2, uint32_t a3,
                                         uint32_t b0, uint32_t b1) {
    asm volatile(
        "mma.sync.aligned.m16n8k8.row.col.f32.tf32.tf32.f32 "
        "{%0,%1,%2,%3}, {%4,%5,%6,%7}, {%8,%9}, {%0,%1,%2,%3};"
        : "+f"(c0), "+f"(c1), "+f"(c2), "+f"(c3)
        : "r"(a0), "r"(a1), "r"(a2), "r"(a3), "r"(b0), "r"(b1));
}
__device__ __forceinline__ float apply_epi(float f, int mode,
                                           const float* __restrict__ bias, int colg) {
    if (mode == 1) {
        f = tanhf(f);
    } else if (mode == 2) {
        float s = 1.0f / (1.0f + expf(-(__ldg(&bias[colg]) + f)));
        f = expf(LOG_W_SCALE * s);
    } else if (mode == 3) {
        f = 1.0f / (1.0f + expf(-(__ldg(&bias[colg]) + f)));
    } else if (mode == 4) {
        f = 1.0f / (1.0f + expf(-f));
    }
    return f;
}
__device__ __forceinline__ uint32_t smem_u32(const void* p) {
    uint32_t a;
    asm("{ .reg .u64 t; cvta.to.shared.u64 t, %1; cvt.u32.u64 %0, t; }"
        : "=r"(a) : "l"(p));
    return a;
}
__device__ __forceinline__ void cp_async16(uint32_t saddr, const void* gptr) {
    asm volatile("cp.async.cg.shared.global [%0], [%1], 16;"
                 :: "r"(saddr), "l"(gptr) : "memory");
}
__device__ __forceinline__ void cp_commit() {
    asm volatile("cp.async.commit_group;" ::: "memory");
}
__device__ __forceinline__ void cp_wait3() {
    asm volatile("cp.async.wait_group 3;" ::: "memory");
}

// ---------------- kernel 1: token-shift mixes ----------------
__global__ void mix_kernel(const float* __restrict__ x,
                           const float* __restrict__ x_x,
                           float* __restrict__ out /* 6 x BTD */) {
    size_t idx = (size_t)blockIdx.x * blockDim.x + threadIdx.x;
    if (idx >= BTD) return;
    int d = (int)(idx & (D_ - 1));
    int t = (int)((idx >> 10) & (T_ - 1));
    float xv = x[idx];
    float prev = (t > 0) ? x[idx - D_] : 0.0f;
    float delta = prev - xv;
#pragma unroll
    for (int j = 0; j < 6; j++) {
        out[(size_t)j * BTD + idx] = xv + delta * __ldg(&x_x[j * D_ + d]);
    }
}

// ---------------- transpose kernel: in[K,N] -> out[N,K] ----------------
__global__ void transpose_kernel(const float* __restrict__ in, float* __restrict__ out,
                                 int K, int N) {
    __shared__ float tile[32][33];
    int n0 = blockIdx.x * 32, k0 = blockIdx.y * 32;
    int tx = threadIdx.x, ty = threadIdx.y;  // 32 x 8
#pragma unroll
    for (int i = 0; i < 32; i += 8) {
        int k = k0 + ty + i, n = n0 + tx;
        if (k < K && n < N) tile[ty + i][tx] = in[(size_t)k * N + n];
    }
    __syncthreads();
#pragma unroll
    for (int i = 0; i < 32; i += 8) {
        int n = n0 + ty + i, k = k0 + tx;
        if (n < N && k < K) out[(size_t)n * K + k] = tile[tx][ty + i];
    }
}

// ---------------- kernel 2: tf32 mma.sync GEMM ----------------
#define SK 36
__global__ __launch_bounds__(256)
void tgemm_kernel(const float* __restrict__ A, const float* __restrict__ Bt,
                  float* __restrict__ C, int M, int N, int K,
                  int mode, const float* __restrict__ bias) {
    __shared__ float As[128][SK];
    __shared__ float Bs[128][SK];

    int tid = threadIdx.x;
    int wid = tid >> 5, lane = tid & 31;
    int warp_m = wid >> 2;
    int warp_n = wid & 3;
    int gid = lane >> 2;
    int tig = lane & 3;
    int block_row = blockIdx.y * 128;
    int block_col = blockIdx.x * 128;

    float acc[4][4][4];
#pragma unroll
    for (int mt = 0; mt < 4; mt++)
#pragma unroll
        for (int nt = 0; nt < 4; nt++)
#pragma unroll
            for (int q = 0; q < 4; q++) acc[mt][nt][q] = 0.0f;

    int lr[4], lc[4];
#pragma unroll
    for (int i = 0; i < 4; i++) {
        int f4 = tid + i * 256;
        lr[i] = f4 >> 3;
        lc[i] = (f4 & 7) * 4;
    }

    float4 ra[4], rb[4];
    int ntiles = K >> 5;

#pragma unroll
    for (int i = 0; i < 4; i++) {
        ra[i] = *(const float4*)(A + (size_t)(block_row + lr[i]) * K + lc[i]);
        int rg = block_col + lr[i];
        rb[i] = (rg < N) ? *(const float4*)(Bt + (size_t)rg * K + lc[i])
                         : make_float4(0.f, 0.f, 0.f, 0.f);
    }

    for (int kt = 0; kt < ntiles; kt++) {
#pragma unroll
        for (int i = 0; i < 4; i++) {
            uint4 va;
            va.x = tf32bits(ra[i].x); va.y = tf32bits(ra[i].y);
            va.z = tf32bits(ra[i].z); va.w = tf32bits(ra[i].w);
            *(uint4*)&As[lr[i]][lc[i]] = va;
            uint4 vb;
            vb.x = tf32bits(rb[i].x); vb.y = tf32bits(rb[i].y);
            vb.z = tf32bits(rb[i].z); vb.w = tf32bits(rb[i].w);
            *(uint4*)&Bs[lr[i]][lc[i]] = vb;
        }
        __syncthreads();

        if (kt + 1 < ntiles) {
            int k0 = (kt + 1) << 5;
#pragma unroll
            for (int i = 0; i < 4; i++) {
                ra[i] = *(const float4*)(A + (size_t)(block_row + lr[i]) * K + k0 + lc[i]);
                int rg = block_col + lr[i];
                rb[i] = (rg < N) ? *(const float4*)(Bt + (size_t)rg * K + k0 + lc[i])
                                 : make_float4(0.f, 0.f, 0.f, 0.f);
            }
        }

#pragma unroll
        for (int ks = 0; ks < 4; ks++) {
            int kk = ks * 8;
            uint32_t af[4][4];
#pragma unroll
            for (int mt = 0; mt < 4; mt++) {
                int r0 = warp_m * 64 + mt * 16 + gid;
                af[mt][0] = __float_as_uint(As[r0][kk + tig]);
                af[mt][1] = __float_as_uint(As[r0 + 8][kk + tig]);
                af[mt][2] = __float_as_uint(As[r0][kk + 4 + tig]);
                af[mt][3] = __float_as_uint(As[r0 + 8][kk + 4 + tig]);
            }
            uint32_t bf[4][2];
#pragma unroll
            for (int nt = 0; nt < 4; nt++) {
                int n0 = warp_n * 32 + nt * 8 + gid;
                bf[nt][0] = __float_as_uint(Bs[n0][kk + tig]);
                bf[nt][1] = __float_as_uint(Bs[n0][kk + 4 + tig]);
            }
#pragma unroll
            for (int mt = 0; mt < 4; mt++)
#pragma unroll
                for (int nt = 0; nt < 4; nt++)
                    mma_tf32(acc[mt][nt][0], acc[mt][nt][1], acc[mt][nt][2], acc[mt][nt][3],
                             af[mt][0], af[mt][1], af[mt][2], af[mt][3],
                             bf[nt][0], bf[nt][1]);
        }
        __syncthreads();
    }

#pragma unroll
    for (int mt = 0; mt < 4; mt++) {
        int row = block_row + warp_m * 64 + mt * 16 + gid;
#pragma unroll
        for (int nt = 0; nt < 4; nt++) {
            int col0 = block_col + warp_n * 32 + nt * 8 + 2 * tig;
            if (col0 < N) {
                float2 v0, v1;
                v0.x = apply_epi(acc[mt][nt][0], mode, bias, col0);
                v0.y = apply_epi(acc[mt][nt][1], mode, bias, col0 + 1);
                v1.x = apply_epi(acc[mt][nt][2], mode, bias, col0);
                v1.y = apply_epi(acc[mt][nt][3], mode, bias, col0 + 1);
                *(float2*)(C + (size_t)row * N + col0) = v0;
                *(float2*)(C + (size_t)(row + 8) * N + col0) = v1;
            }
        }
    }
}

// ---------------- kernel 3: prep ----------------
__global__ void prep_kernel(float* __restrict__ Kb, float* __restrict__ Vb,
                            const float* __restrict__ Ab, const float* __restrict__ VMIXb,
                            const float* __restrict__ vfirst,
                            const float* __restrict__ k_k, const float* __restrict__ k_a,
                            float* __restrict__ AKK, float* __restrict__ BKK) {
    int bt = blockIdx.x;
    int lane = threadIdx.x & 31;
    int h = threadIdx.x >> 5;
    int d0 = h * HD_ + lane, d1 = d0 + 32;
    size_t i0 = (size_t)bt * D_ + d0;
    size_t i1 = i0 + 32;

    float k0 = Kb[i0], k1 = Kb[i1];
    float kk0 = k0 * __ldg(&k_k[d0]);
    float kk1 = k1 * __ldg(&k_k[d1]);
    float ss = kk0 * kk0 + kk1 * kk1;
#pragma unroll
    for (int o = 16; o > 0; o >>= 1) ss += __shfl_xor_sync(0xffffffffu, ss, o);
    float inv = 1.0f / fmaxf(sqrtf(ss), 1e-12f);
    kk0 *= inv; kk1 *= inv;

    float a0v = Ab[i0], a1v = Ab[i1];
    AKK[i0] = -kk0;        AKK[i1] = -kk1;
    BKK[i0] = kk0 * a0v;   BKK[i1] = kk1 * a1v;

    Kb[i0] = k0 * (1.0f + (a0v - 1.0f) * __ldg(&k_a[d0]));
    Kb[i1] = k1 * (1.0f + (a1v - 1.0f) * __ldg(&k_a[d1]));

    float v0v = Vb[i0], v1v = Vb[i1];
    Vb[i0] = v0v + (vfirst[i0] - v0v) * VMIXb[i0];
    Vb[i1] = v1v + (vfirst[i1] - v1v) * VMIXb[i1];
}

// ---------------- kernel 4: scan with cp.async 4-stage pipeline ----------------
// SC points at R; arrays at SC + arr*BTD: R(0) EW(1) K(2) V(3) AKK(4) BKK(5)
// 256 threads: row i = tid>>2 (64 rows), col-group c = tid&3 (16 cols each)
__global__ __launch_bounds__(256, 1)
void scan_kernel(const float* __restrict__ SC, float* __restrict__ O) {
    int b = blockIdx.x >> 4;
    int h = blockIdx.x & 15;
    int tid = threadIdx.x;
    int i = tid >> 2;
    int c = tid & 3;
    int cb = c * 16;

    __shared__ __align__(16) float sh[4][6][64];

    float S[16];
#pragma unroll
    for (int j = 0; j < 16; j++) S[j] = 0.0f;

    size_t base = (size_t)b * T_ * D_ + (size_t)h * HD_;
    const unsigned FULL = 0xffffffffu;
    uint32_t sh_base = smem_u32(sh);

    // copy assignment: threads 0..95 each move one float4 (6 arrays x 16 f4)
    int arr = tid >> 4;          // 0..5 (valid when tid < 96)
    int el  = (tid & 15) << 2;   // 0,4,...,60

    // prefetch stages 0..3
#pragma unroll
    for (int t = 0; t < 4; t++) {
        if (tid < 96) {
            const float* g = SC + (size_t)arr * BTD + base + (size_t)t * D_ + el;
            cp_async16(sh_base + (uint32_t)(((t * 6 + arr) * 64 + el) * 4), g);
        }
        cp_commit();
    }

    for (int t = 0; t < T_; t++) {
        cp_wait3();
        __syncthreads();

        int s = t & 3;
        const float* st0 = &sh[s][0][0];  // R
        const float* st1 = &sh[s][1][0];  // EW
        const float* st2 = &sh[s][2][0];  // K
        const float* st3 = &sh[s][3][0];  // V
        const float* st4 = &sh[s][4][0];  // AKK
        const float* st5 = &sh[s][5][0];  // BKK

        float sa = 0.0f;
#pragma unroll
        for (int q = 0; q < 4; q++) {
            float4 a4 = *(const float4*)(st4 + cb + q * 4);
            sa += S[q * 4 + 0] * a4.x + S[q * 4 + 1] * a4.y
                + S[q * 4 + 2] * a4.z + S[q * 4 + 3] * a4.w;
        }
        sa += __shfl_xor_sync(FULL, sa, 1);
        sa += __shfl_xor_sync(FULL, sa, 2);

        float vi = st3[i];
        float op = 0.0f;
#pragma unroll
        for (int q = 0; q < 4; q++) {
            float4 w4 = *(const float4*)(st1 + cb + q * 4);
            float4 k4 = *(const float4*)(st2 + cb + q * 4);
            float4 b4 = *(const float4*)(st5 + cb + q * 4);
            float4 r4 = *(const float4*)(st0 + cb + q * 4);
            S[q * 4 + 0] = S[q * 4 + 0] * w4.x + (sa * b4.x + vi * k4.x);
            S[q * 4 + 1] = S[q * 4 + 1] * w4.y + (sa * b4.y + vi * k4.y);
            S[q * 4 + 2] = S[q * 4 + 2] * w4.z + (sa * b4.z + vi * k4.z);
            S[q * 4 + 3] = S[q * 4 + 3] * w4.w + (sa * b4.w + vi * k4.w);
            op += S[q * 4 + 0] * r4.x + S[q * 4 + 1] * r4.y
                + S[q * 4 + 2] * r4.z + S[q * 4 + 3] * r4.w;
        }
        op += __shfl_xor_sync(FULL, op, 1);
        op += __shfl_xor_sync(FULL, op, 2);
        if (c == 0) O[base + (size_t)t * D_ + i] = op;

        __syncthreads();

        int tn = t + 4;
        if (tn < T_ && tid < 96) {
            const float* g = SC + (size_t)arr * BTD + base + (size_t)tn * D_ + el;
            cp_async16(sh_base + (uint32_t)(((s * 6 + arr) * 64 + el) * 4), g);
        }
        cp_commit();
    }
}

// ---------------- kernel 5: groupnorm + bonus + gate ----------------
__global__ void post_kernel(const float* __restrict__ O, const float* __restrict__ R,
                            const float* __restrict__ Kb, const float* __restrict__ Vb,
                            const float* __restrict__ G, const float* __restrict__ r_k,
                            const float* __restrict__ gn_w, const float* __restrict__ gn_b,
                            float* __restrict__ GATED) {
    int bt = blockIdx.x;
    int lane = threadIdx.x & 31;
    int h = threadIdx.x >> 5;
    int d0 = h * HD_ + lane, d1 = d0 + 32;
    size_t i0 = (size_t)bt * D_ + d0;
    size_t i1 = i0 + 32;

    float o0 = O[i0], o1 = O[i1];
    float s = o0 + o1;
    float sq = o0 * o0 + o1 * o1;
    float dot = R[i0] * Kb[i0] * __ldg(&r_k[d0]) + R[i1] * Kb[i1] * __ldg(&r_k[d1]);
#pragma unroll
    for (int o = 16; o > 0; o >>= 1) {
        s   += __shfl_xor_sync(0xffffffffu, s, o);
        sq  += __shfl_xor_sync(0xffffffffu, sq, o);
        dot += __shfl_xor_sync(0xffffffffu, dot, o);
    }
    float mean = s * (1.0f / 64.0f);
    float var = sq * (1.0f / 64.0f) - mean * mean;
    float rstd = rsqrtf(var + GN_EPS);
    float on0 = (o0 - mean) * rstd * __ldg(&gn_w[d0]) + __ldg(&gn_b[d0]);
    float on1 = (o1 - mean) * rstd * __ldg(&gn_w[d1]) + __ldg(&gn_b[d1]);
    on0 += dot * Vb[i0];
    on1 += dot * Vb[i1];
    GATED[i0] = on0 * G[i0];
    GATED[i1] = on1 * G[i1];
}

// ---------------- host launchers ----------------
static void run_tgemm(const float* A, const float* Bt, float* C,
                      int M, int N, int K, int mode, const float* bias) {
    dim3 grid((N + 127) / 128, M / 128);
    tgemm_kernel<<<grid, 256>>>(A, Bt, C, M, N, K, mode, bias);
}
static void run_transpose(const float* in, float* out, int K, int N) {
    dim3 grid((N + 31) / 32, (K + 31) / 32);
    transpose_kernel<<<grid, dim3(32, 8)>>>(in, out, K, N);
}

extern "C" void kernel_launch(void* const* d_in, const int* in_sizes, int n_in,
                              void* d_out, int out_size) {
    const float* x       = (const float*)d_in[0];
    const float* v_first = (const float*)d_in[1];
    const float* x_x     = (const float*)d_in[2];
    const float* W_r     = (const float*)d_in[3];
    const float* W_k     = (const float*)d_in[4];
    const float* W_v     = (const float*)d_in[5];
    const float* W_o     = (const float*)d_in[6];
    const float* w1      = (const float*)d_in[7];
    const float* w2      = (const float*)d_in[8];
    const float* w0      = (const float*)d_in[9];
    const float* a1      = (const float*)d_in[10];
    const float* a2      = (const float*)d_in[11];
    const float* a0      = (const float*)d_in[12];
    const float* v1      = (const float*)d_in[13];
    const float* v2      = (const float*)d_in[14];
    const float* v0      = (const float*)d_in[15];
    const float* g1      = (const float*)d_in[16];
    const float* g2      = (const float*)d_in[17];
    const float* k_k     = (const float*)d_in[18];
    const float* k_a     = (const float*)d_in[19];
    const float* r_k     = (const float*)d_in[20];
    const float* gn_w    = (const float*)d_in[21];
    const float* gn_b    = (const float*)d_in[22];
    float* out = (float*)d_out;

    float* sc;
    cudaGetSymbolAddress((void**)&sc, g_scratch);

    float* XR    = sc + 0 * BTD;
    float* XW    = sc + 1 * BTD;
    float* XK    = sc + 2 * BTD;
    float* XV    = sc + 3 * BTD;
    float* XA    = sc + 4 * BTD;
    float* XG    = sc + 5 * BTD;
    float* Rb    = sc + 6 * BTD;
    float* EWb   = sc + 7 * BTD;
    float* Kb    = sc + 8 * BTD;
    float* Vb    = sc + 9 * BTD;
    float* AKKb  = sc + 10 * BTD;
    float* BKKb  = sc + 11 * BTD;
    float* Ab    = sc + 12 * BTD;
    float* VMIXb = sc + 13 * BTD;
    float* Ob    = sc + 14 * BTD;
    float* Gb    = sc + 15 * BTD;
    float* GATED = sc + 16 * BTD;
    float* T1b   = sc + T1_OFF;
    float* T2b   = sc + T2_OFF;
    float* T3b   = sc + T3_OFF;
    float* T4b   = sc + T4_OFF;
    float* WRT   = sc + WRT_OFF;
    float* WKT   = sc + WKT_OFF;
    float* WVT   = sc + WVT_OFF;
    float* WOT   = sc + WOT_OFF;
    float* W1T   = sc + W1T_OFF;
    float* W2T   = sc + W2T_OFF;
    float* A1T   = sc + A1T_OFF;
    float* A2T   = sc + A2T_OFF;
    float* V1T   = sc + V1T_OFF;
    float* V2T   = sc + V2T_OFF;
    float* G1T   = sc + G1T_OFF;
    float* G2T   = sc + G2T_OFF;

    // 0. weight transposes ([K,N] -> [N,K])
    run_transpose(W_r, WRT, D_, D_);
    run_transpose(W_k, WKT, D_, D_);
    run_transpose(W_v, WVT, D_, D_);
    run_transpose(W_o, WOT, D_, D_);
    run_transpose(w1, W1T, D_, 64);
    run_transpose(w2, W2T, 64, D_);
    run_transpose(a1, A1T, D_, 64);
    run_transpose(a2, A2T, 64, D_);
    run_transpose(v1, V1T, D_, 32);
    run_transpose(v2, V2T, 32, D_);
    run_transpose(g1, G1T, D_, 160);
    run_transpose(g2, G2T, 160, D_);

    // 1. token-shift mixes
    mix_kernel<<<(unsigned)((BTD + 255) / 256), 256>>>(x, x_x, XR);

    // 2. big projections
    run_tgemm(XR, WRT, Rb, (int)BT, D_, D_, 0, nullptr);
    run_tgemm(XK, WKT, Kb, (int)BT, D_, D_, 0, nullptr);
    run_tgemm(XV, WVT, Vb, (int)BT, D_, D_, 0, nullptr);

    // 3. low-rank chains
    run_tgemm(XW, W1T, T1b, (int)BT, 64, D_, 1, nullptr);
    run_tgemm(T1b, W2T, EWb, (int)BT, D_, 64, 2, w0);
    run_tgemm(XA, A1T, T2b, (int)BT, 64, D_, 0, nullptr);
    run_tgemm(T2b, A2T, Ab, (int)BT, D_, 64, 3, a0);
    run_tgemm(XV, V1T, T3b, (int)BT, 32, D_, 0, nullptr);
    run_tgemm(T3b, V2T, VMIXb, (int)BT, D_, 32, 3, v0);
    run_tgemm(XG, G1T, T4b, (int)BT, 160, D_, 4, nullptr);
    run_tgemm(T4b, G2T, Gb, (int)BT, D_, 160, 0, nullptr);

    // 4. prep
    prep_kernel<<<(unsigned)BT, 512>>>(Kb, Vb, Ab, VMIXb, v_first, k_k, k_a, AKKb, BKKb);

    // 5. sequential scan (pipelined)
    scan_kernel<<<B_ * H_, 256>>>(Rb, Ob);

    // 6. groupnorm + bonus + gate
    post_kernel<<<(unsigned)BT, 512>>>(Ob, Rb, Kb, Vb, Gb, r_k, gn_w, gn_b, GATED);

    // 7. output projection
    run_tgemm(GATED, WOT, out, (int)BT, D_, D_, 0, nullptr);

    // 8. v_first passthrough
    if ((size_t)out_size >= 2 * BTD) {
        cudaMemcpyAsync(out + BTD, v_first, BTD * sizeof(float),
                        cudaMemcpyDeviceToDevice, 0);
    }
}